// round 2
// baseline (speedup 1.0000x reference)
#include <cuda_runtime.h>
#include <cuda_bf16.h>
#include <math.h>

// Problem constants
#define BATCH 2
#define SEQ   2048
#define EMB   1024
#define HEADS 16
#define HDIM  64
#define ROWS  (BATCH * SEQ)   // 4096

// -------------------- scratch (allocation-free: device globals) --------------------
__device__ float g_Q[ROWS * EMB];
__device__ float g_K[ROWS * EMB];
__device__ float g_V[ROWS * EMB];
__device__ float g_O[ROWS * EMB];

// ==================================================================================
// SGEMM: C[m][n] = sum_k A[m][k] * B[n][k] + bias[n]   (i.e. C = A @ B^T + bias)
// A: (M,K) row-major, B: (N,K) row-major. M,N,K multiples of 128/128/16.
// BM=BN=128, BK=16, 256 threads, 8x8 per-thread tile.
// ==================================================================================
__global__ __launch_bounds__(256, 2)
void sgemm_bias_kernel(const float* __restrict__ A, const float* __restrict__ B,
                       const float* __restrict__ bias, float* __restrict__ C,
                       int M, int N, int K)
{
    __shared__ float As[16][128];
    __shared__ float Bs[16][128];

    const int tid = threadIdx.x;
    const int tx = tid % 16;       // 16 col groups
    const int ty = tid / 16;       // 16 row groups
    const int m0 = blockIdx.y * 128;
    const int n0 = blockIdx.x * 128;

    const int ldRow = tid / 4;         // 0..63
    const int ldCol = (tid % 4) * 4;   // 0,4,8,12

    float acc[8][8];
#pragma unroll
    for (int i = 0; i < 8; i++)
#pragma unroll
        for (int j = 0; j < 8; j++) acc[i][j] = 0.0f;

    for (int k0 = 0; k0 < K; k0 += 16) {
        // load A tile (transposed into As[k][m])
#pragma unroll
        for (int r = 0; r < 2; r++) {
            const int row = ldRow + r * 64;
            float4 v = *(const float4*)(A + (size_t)(m0 + row) * K + k0 + ldCol);
            As[ldCol + 0][row] = v.x;
            As[ldCol + 1][row] = v.y;
            As[ldCol + 2][row] = v.z;
            As[ldCol + 3][row] = v.w;
        }
        // load B tile (transposed into Bs[k][n])
#pragma unroll
        for (int r = 0; r < 2; r++) {
            const int row = ldRow + r * 64;
            float4 v = *(const float4*)(B + (size_t)(n0 + row) * K + k0 + ldCol);
            Bs[ldCol + 0][row] = v.x;
            Bs[ldCol + 1][row] = v.y;
            Bs[ldCol + 2][row] = v.z;
            Bs[ldCol + 3][row] = v.w;
        }
        __syncthreads();

#pragma unroll
        for (int kk = 0; kk < 16; kk++) {
            float ra[8], rb[8];
#pragma unroll
            for (int i = 0; i < 8; i++) ra[i] = As[kk][ty * 8 + i];
#pragma unroll
            for (int j = 0; j < 8; j++) rb[j] = Bs[kk][tx * 8 + j];
#pragma unroll
            for (int i = 0; i < 8; i++)
#pragma unroll
                for (int j = 0; j < 8; j++)
                    acc[i][j] = fmaf(ra[i], rb[j], acc[i][j]);
        }
        __syncthreads();
    }

    // epilogue
#pragma unroll
    for (int i = 0; i < 8; i++) {
        const int row = m0 + ty * 8 + i;
        float* crow = C + (size_t)row * N + n0 + tx * 8;
#pragma unroll
        for (int j = 0; j < 8; j += 4) {
            float4 v;
            v.x = acc[i][j + 0];
            v.y = acc[i][j + 1];
            v.z = acc[i][j + 2];
            v.w = acc[i][j + 3];
            if (bias) {
                const float* bp = bias + n0 + tx * 8 + j;
                v.x += bp[0]; v.y += bp[1]; v.z += bp[2]; v.w += bp[3];
            }
            *(float4*)(crow + j) = v;
        }
    }
}

// ==================================================================================
// Flash-style attention, fp32.
// grid = (S/64 q-tiles, B*H). block = 256 threads.
// Per block: Q tile (64 x 64) resident in smem, loop over 32 K/V tiles of 64 rows.
// Online softmax with additive bias[h, q, k]. Output written as (B, S, H*D) layout.
// ==================================================================================
#define LDS 65   // padded stride for 64-wide fp32 tiles
#define ATTN_SMEM_FLOATS (4 * 64 * LDS)
#define ATTN_SMEM_BYTES  (ATTN_SMEM_FLOATS * sizeof(float))

__global__ __launch_bounds__(256, 1)
void attn_kernel(const float* __restrict__ Q, const float* __restrict__ K,
                 const float* __restrict__ V, const float* __restrict__ bias,
                 float* __restrict__ O)
{
    extern __shared__ float sm[];
    float* sQ = sm;
    float* sK = sQ + 64 * LDS;
    float* sV = sK + 64 * LDS;
    float* sP = sV + 64 * LDS;

    const int bh = blockIdx.y;        // b*HEADS + h
    const int b = bh / HEADS;
    const int h = bh % HEADS;
    const int q0 = blockIdx.x * 64;

    const int tid = threadIdx.x;
    const int tx = tid % 16;     // column group (4 cols each)
    const int ty = tid / 16;     // row group (4 rows each)
    const int r0 = ty * 4;
    const int c0 = tx * 4;

    const float scale = 0.125f;  // 1/sqrt(64)

    // ---- load Q tile (pre-scaled) ----
    const float* Qbase = Q + ((size_t)(b * SEQ + q0)) * EMB + h * HDIM;
    for (int idx = tid; idx < 64 * 16; idx += 256) {
        const int r = idx / 16;
        const int c4 = (idx % 16) * 4;
        float4 v = *(const float4*)(Qbase + (size_t)r * EMB + c4);
        sQ[r * LDS + c4 + 0] = v.x * scale;
        sQ[r * LDS + c4 + 1] = v.y * scale;
        sQ[r * LDS + c4 + 2] = v.z * scale;
        sQ[r * LDS + c4 + 3] = v.w * scale;
    }

    float m_i[4], l_i[4], o[4][4];
#pragma unroll
    for (int i = 0; i < 4; i++) {
        m_i[i] = -INFINITY;
        l_i[i] = 0.0f;
#pragma unroll
        for (int j = 0; j < 4; j++) o[i][j] = 0.0f;
    }

    const float* biasbase = bias + ((size_t)h * SEQ + q0) * SEQ;

    for (int kt = 0; kt < SEQ / 64; kt++) {
        const int k0 = kt * 64;
        __syncthreads();  // prior sP/sK/sV consumers done

        // ---- load K & V tiles ----
        const float* Kbase = K + ((size_t)(b * SEQ + k0)) * EMB + h * HDIM;
        const float* Vbase = V + ((size_t)(b * SEQ + k0)) * EMB + h * HDIM;
        for (int idx = tid; idx < 64 * 16; idx += 256) {
            const int r = idx / 16;
            const int c4 = (idx % 16) * 4;
            float4 kv = *(const float4*)(Kbase + (size_t)r * EMB + c4);
            sK[r * LDS + c4 + 0] = kv.x;
            sK[r * LDS + c4 + 1] = kv.y;
            sK[r * LDS + c4 + 2] = kv.z;
            sK[r * LDS + c4 + 3] = kv.w;
            float4 vv = *(const float4*)(Vbase + (size_t)r * EMB + c4);
            sV[r * LDS + c4 + 0] = vv.x;
            sV[r * LDS + c4 + 1] = vv.y;
            sV[r * LDS + c4 + 2] = vv.z;
            sV[r * LDS + c4 + 3] = vv.w;
        }
        __syncthreads();

        // ---- S = (Q*scale) @ K^T  (4x4 per thread) ----
        float s[4][4];
#pragma unroll
        for (int i = 0; i < 4; i++)
#pragma unroll
            for (int j = 0; j < 4; j++) s[i][j] = 0.0f;

#pragma unroll 4
        for (int d = 0; d < 64; d++) {
            float qa[4], kb[4];
#pragma unroll
            for (int i = 0; i < 4; i++) qa[i] = sQ[(r0 + i) * LDS + d];
#pragma unroll
            for (int j = 0; j < 4; j++) kb[j] = sK[(c0 + j) * LDS + d];
#pragma unroll
            for (int i = 0; i < 4; i++)
#pragma unroll
                for (int j = 0; j < 4; j++)
                    s[i][j] = fmaf(qa[i], kb[j], s[i][j]);
        }

        // ---- add bias ----
#pragma unroll
        for (int i = 0; i < 4; i++) {
            float4 bv = *(const float4*)(biasbase + (size_t)(r0 + i) * SEQ + k0 + c0);
            s[i][0] += bv.x; s[i][1] += bv.y; s[i][2] += bv.z; s[i][3] += bv.w;
        }

        // ---- online softmax (row groups of 16 lanes within each warp half) ----
#pragma unroll
        for (int i = 0; i < 4; i++) {
            float t = fmaxf(fmaxf(s[i][0], s[i][1]), fmaxf(s[i][2], s[i][3]));
#pragma unroll
            for (int off = 8; off >= 1; off >>= 1)
                t = fmaxf(t, __shfl_xor_sync(0xffffffffu, t, off));
            const float mnew = fmaxf(m_i[i], t);
            const float alpha = __expf(m_i[i] - mnew);
            float rs = 0.0f;
#pragma unroll
            for (int j = 0; j < 4; j++) {
                s[i][j] = __expf(s[i][j] - mnew);
                rs += s[i][j];
            }
#pragma unroll
            for (int off = 8; off >= 1; off >>= 1)
                rs += __shfl_xor_sync(0xffffffffu, rs, off);
            l_i[i] = l_i[i] * alpha + rs;
            m_i[i] = mnew;
#pragma unroll
            for (int j = 0; j < 4; j++) o[i][j] *= alpha;
            // stash P tile
            sP[(r0 + i) * LDS + c0 + 0] = s[i][0];
            sP[(r0 + i) * LDS + c0 + 1] = s[i][1];
            sP[(r0 + i) * LDS + c0 + 2] = s[i][2];
            sP[(r0 + i) * LDS + c0 + 3] = s[i][3];
        }
        __syncthreads();

        // ---- O += P @ V  (thread owns rows r0..r0+3, d-cols c0..c0+3) ----
#pragma unroll 4
        for (int j = 0; j < 64; j++) {
            float pv[4], vv[4];
#pragma unroll
            for (int i = 0; i < 4; i++) pv[i] = sP[(r0 + i) * LDS + j];
#pragma unroll
            for (int jj = 0; jj < 4; jj++) vv[jj] = sV[j * LDS + c0 + jj];
#pragma unroll
            for (int i = 0; i < 4; i++)
#pragma unroll
                for (int jj = 0; jj < 4; jj++)
                    o[i][jj] = fmaf(pv[i], vv[jj], o[i][jj]);
        }
    }

    // ---- normalize + write out in (B, S, H*D) layout ----
    float* Obase = O + ((size_t)(b * SEQ + q0)) * EMB + h * HDIM;
#pragma unroll
    for (int i = 0; i < 4; i++) {
        const float inv = 1.0f / l_i[i];
        float4 v;
        v.x = o[i][0] * inv;
        v.y = o[i][1] * inv;
        v.z = o[i][2] * inv;
        v.w = o[i][3] * inv;
        *(float4*)(Obase + (size_t)(r0 + i) * EMB + c0) = v;
    }
}

// ==================================================================================
// Launch
// ==================================================================================
extern "C" void kernel_launch(void* const* d_in, const int* in_sizes, int n_in,
                              void* d_out, int out_size)
{
    const float* X    = (const float*)d_in[0];  // (B,S,E)
    const float* bias = (const float*)d_in[1];  // (1,H,S,S)
    const float* Wq   = (const float*)d_in[2];
    const float* bq   = (const float*)d_in[3];
    const float* Wk   = (const float*)d_in[4];
    const float* bk   = (const float*)d_in[5];
    const float* Wv   = (const float*)d_in[6];
    const float* bv   = (const float*)d_in[7];
    const float* Wo   = (const float*)d_in[8];
    float* out = (float*)d_out;

    float *Qp, *Kp, *Vp, *Op;
    cudaGetSymbolAddress((void**)&Qp, g_Q);
    cudaGetSymbolAddress((void**)&Kp, g_K);
    cudaGetSymbolAddress((void**)&Vp, g_V);
    cudaGetSymbolAddress((void**)&Op, g_O);

    cudaFuncSetAttribute(attn_kernel,
                         cudaFuncAttributeMaxDynamicSharedMemorySize,
                         ATTN_SMEM_BYTES);

    dim3 ggrid(EMB / 128, ROWS / 128);  // (8, 32)
    sgemm_bias_kernel<<<ggrid, 256>>>(X, Wq, bq, Qp, ROWS, EMB, EMB);
    sgemm_bias_kernel<<<ggrid, 256>>>(X, Wk, bk, Kp, ROWS, EMB, EMB);
    sgemm_bias_kernel<<<ggrid, 256>>>(X, Wv, bv, Vp, ROWS, EMB, EMB);

    dim3 agrid(SEQ / 64, BATCH * HEADS);  // (32, 32)
    attn_kernel<<<agrid, 256, ATTN_SMEM_BYTES>>>(Qp, Kp, Vp, bias, Op);

    sgemm_bias_kernel<<<ggrid, 256>>>(Op, Wo, nullptr, out, ROWS, EMB, EMB);
}